// round 1
// baseline (speedup 1.0000x reference)
#include <cuda_runtime.h>
#include <cstdint>

// ---------------------------------------------------------------------------
// Problem constants
//   x  : [8, 2048, 512]  fp32
//   Wq/Wk/Wv : [512, 512], bq/bk/bv : [512]
//   out: [8, 2048, 1024] = concat(x, attn_out)
// ---------------------------------------------------------------------------
#define BATCH   8
#define SEQ     2048
#define DMODEL  512
#define ROWS    (BATCH * SEQ)        // 16384
#define SCALE   0.044194173824159216f // 1/sqrt(512)

// Scratch (allocation-free rule: __device__ globals)
__device__ float g_Q[ROWS * DMODEL];
__device__ float g_K[ROWS * DMODEL];
__device__ float g_V[ROWS * DMODEL];

// ---------------------------------------------------------------------------
// Kernel 1: copy x into out[..., 0:512]
// ---------------------------------------------------------------------------
__global__ void __launch_bounds__(256) copy_x_kernel(const float* __restrict__ x,
                                                     float* __restrict__ out) {
    int idx = blockIdx.x * 256 + threadIdx.x;     // float4 index, 2,097,152 total
    int row = idx >> 7;                           // 128 float4 per 512-float row
    int c   = (idx & 127) * 4;
    *(float4*)(out + (size_t)row * 1024 + c) =
        *(const float4*)(x + (size_t)row * 512 + c);
}

// ---------------------------------------------------------------------------
// Kernel 2: QKV projection GEMM.  C[16384,512] = X[16384,512] @ W[512,512] + b
// 128x128 tile, BK=8, 256 threads, 8x8 micro-tile per thread.
// grid = (4, 128, 3); z selects (Wq,bq,g_Q) / (Wk,bk,g_K) / (Wv,bv,g_V)
// ---------------------------------------------------------------------------
__global__ void __launch_bounds__(256) qkv_gemm_kernel(
    const float* __restrict__ X,
    const float* __restrict__ W0, const float* __restrict__ b0,
    const float* __restrict__ W1, const float* __restrict__ b1,
    const float* __restrict__ W2, const float* __restrict__ b2) {

    const float* W; const float* bias; float* C;
    if (blockIdx.z == 0)      { W = W0; bias = b0; C = g_Q; }
    else if (blockIdx.z == 1) { W = W1; bias = b1; C = g_K; }
    else                      { W = W2; bias = b2; C = g_V; }

    __shared__ float As[8][128];   // A tile, transposed: As[k][m]
    __shared__ float Bs[8][128];   // B tile: Bs[k][n]

    const int t  = threadIdx.x;
    const int tx = t & 15;         // N direction (16)
    const int ty = t >> 4;         // M direction (16)
    const int bm = blockIdx.y;     // 128 M-tiles
    const int bn = blockIdx.x;     // 4 N-tiles

    float acc[8][8];
#pragma unroll
    for (int i = 0; i < 8; i++)
#pragma unroll
        for (int j = 0; j < 8; j++) acc[i][j] = 0.f;

    const int arow = t >> 1;            // 0..127
    const int acol = (t & 1) * 4;       // 0 or 4
    const int brow = t >> 5;            // 0..7
    const int bcol = (t & 31) * 4;      // 0..124

    const float* Ag = X + (size_t)(bm * 128 + arow) * 512 + acol;
    const float* Bg = W + (size_t)brow * 512 + bn * 128 + bcol;

    for (int k0 = 0; k0 < 512; k0 += 8) {
        float4 a  = *(const float4*)(Ag + k0);
        float4 bv = *(const float4*)(Bg + (size_t)k0 * 512);
        __syncthreads();                 // previous iter's reads done
        As[acol + 0][arow] = a.x;
        As[acol + 1][arow] = a.y;
        As[acol + 2][arow] = a.z;
        As[acol + 3][arow] = a.w;
        *(float4*)&Bs[brow][bcol] = bv;
        __syncthreads();

#pragma unroll
        for (int kk = 0; kk < 8; kk++) {
            float4 a0 = *(const float4*)&As[kk][ty * 4];
            float4 a1 = *(const float4*)&As[kk][ty * 4 + 64];
            float4 c0 = *(const float4*)&Bs[kk][tx * 4];
            float4 c1 = *(const float4*)&Bs[kk][tx * 4 + 64];
            float av[8] = {a0.x, a0.y, a0.z, a0.w, a1.x, a1.y, a1.z, a1.w};
            float bw[8] = {c0.x, c0.y, c0.z, c0.w, c1.x, c1.y, c1.z, c1.w};
#pragma unroll
            for (int i = 0; i < 8; i++)
#pragma unroll
                for (int j = 0; j < 8; j++) acc[i][j] += av[i] * bw[j];
        }
    }

    // Epilogue: rows ty*4 + {0..3, 64..67}; cols tx*4 + {0..3, 64..67}
    const int col0 = bn * 128 + tx * 4;
    float4 bias0 = *(const float4*)(bias + col0);
    float4 bias1 = *(const float4*)(bias + col0 + 64);
#pragma unroll
    for (int rm = 0; rm < 8; rm++) {
        int row = bm * 128 + ty * 4 + (rm & 3) + ((rm >> 2) * 64);
        float* Crow = C + (size_t)row * 512;
        float4 r0 = make_float4(acc[rm][0] + bias0.x, acc[rm][1] + bias0.y,
                                acc[rm][2] + bias0.z, acc[rm][3] + bias0.w);
        float4 r1 = make_float4(acc[rm][4] + bias1.x, acc[rm][5] + bias1.y,
                                acc[rm][6] + bias1.z, acc[rm][7] + bias1.w);
        *(float4*)(Crow + col0)      = r0;
        *(float4*)(Crow + col0 + 64) = r1;
    }
}

// ---------------------------------------------------------------------------
// Kernel 3: causal flash attention, fp32, writes out[..., 512:1024]
// Block = 32 queries of one batch, 256 threads.
// Thread (i = t/8, g = t%8) owns query row i's d-subset {g*4 + 32k + c}
// (strided float4 chunks -> all-32-bank conflict-free LDS with 4-way broadcast).
// Q and O live entirely in registers (64 regs each). K/V tiles of 16 rows
// share one 32KB smem buffer. Online softmax replicated per row via shfl.
// ---------------------------------------------------------------------------
#define BQ 32
#define BK 16

__global__ void __launch_bounds__(256) attn_kernel(float* __restrict__ out) {
    __shared__ float KVs[BK][DMODEL];   // 32 KB, reused for K then V

    const int t  = threadIdx.x;
    const int g  = t & 7;
    const int i  = t >> 3;                       // query row within tile
    const int b  = blockIdx.y;
    const int qt = (gridDim.x - 1) - blockIdx.x; // heaviest tiles first
    const int q0 = qt * BQ;
    const int qi = q0 + i;

    const float* Kb = g_K + (size_t)b * SEQ * DMODEL;
    const float* Vb = g_V + (size_t)b * SEQ * DMODEL;

    // Q row -> registers (strided subset)
    float4 q[16];
    {
        const float* qrow = g_Q + ((size_t)b * SEQ + qi) * DMODEL + g * 4;
#pragma unroll
        for (int k = 0; k < 16; k++) q[k] = *(const float4*)(qrow + k * 32);
    }

    float4 o[16];
#pragma unroll
    for (int k = 0; k < 16; k++) o[k] = make_float4(0.f, 0.f, 0.f, 0.f);

    float m = -INFINITY;
    float l = 0.f;

    const int ntiles = (q0 + BQ) / BK;   // exact: covers keys 0..q0+31

    for (int kt = 0; kt < ntiles; kt++) {
        const int kbase = kt * BK;

        // --- load K tile ---
        __syncthreads();   // prior PV reads of KVs complete
#pragma unroll
        for (int idx = t; idx < BK * (DMODEL / 4); idx += 256) {
            int row = idx >> 7;
            int c4  = (idx & 127) * 4;
            *(float4*)&KVs[row][c4] =
                *(const float4*)(Kb + (size_t)(kbase + row) * DMODEL + c4);
        }
        __syncthreads();

        // --- scores: partial dot over this thread's d-subset, shfl-reduce ---
        float s[BK];
#pragma unroll
        for (int j = 0; j < BK; j++) {
            float acc = 0.f;
#pragma unroll
            for (int k = 0; k < 16; k++) {
                float4 kv = *(const float4*)&KVs[j][g * 4 + k * 32];
                acc += q[k].x * kv.x + q[k].y * kv.y + q[k].z * kv.z + q[k].w * kv.w;
            }
            acc += __shfl_xor_sync(0xffffffffu, acc, 1);
            acc += __shfl_xor_sync(0xffffffffu, acc, 2);
            acc += __shfl_xor_sync(0xffffffffu, acc, 4);
            s[j] = (kbase + j <= qi) ? acc * SCALE : -INFINITY;
        }

        // --- online softmax (replicated across the 8 g-lanes of a row) ---
        float mt = s[0];
#pragma unroll
        for (int j = 1; j < BK; j++) mt = fmaxf(mt, s[j]);
        float m_new = fmaxf(m, mt);
        float alpha = __expf(m - m_new);    // exp(-inf)=0 on first tile
        float p[BK];
        float psum = 0.f;
#pragma unroll
        for (int j = 0; j < BK; j++) { p[j] = __expf(s[j] - m_new); psum += p[j]; }
        l = l * alpha + psum;
        m = m_new;
#pragma unroll
        for (int k = 0; k < 16; k++) {
            o[k].x *= alpha; o[k].y *= alpha; o[k].z *= alpha; o[k].w *= alpha;
        }

        // --- load V tile (same buffer) ---
        __syncthreads();
#pragma unroll
        for (int idx = t; idx < BK * (DMODEL / 4); idx += 256) {
            int row = idx >> 7;
            int c4  = (idx & 127) * 4;
            *(float4*)&KVs[row][c4] =
                *(const float4*)(Vb + (size_t)(kbase + row) * DMODEL + c4);
        }
        __syncthreads();

        // --- PV accumulate ---
#pragma unroll
        for (int j = 0; j < BK; j++) {
            float pj = p[j];
#pragma unroll
            for (int k = 0; k < 16; k++) {
                float4 vv = *(const float4*)&KVs[j][g * 4 + k * 32];
                o[k].x += pj * vv.x; o[k].y += pj * vv.y;
                o[k].z += pj * vv.z; o[k].w += pj * vv.w;
            }
        }
    }

    // --- normalize + write out[..., 512 + d] ---
    const float inv = 1.f / l;
    float* orow = out + ((size_t)b * SEQ + qi) * 1024 + 512 + g * 4;
#pragma unroll
    for (int k = 0; k < 16; k++) {
        float4 v = make_float4(o[k].x * inv, o[k].y * inv, o[k].z * inv, o[k].w * inv);
        *(float4*)(orow + k * 32) = v;
    }
}

// ---------------------------------------------------------------------------
// Launch (graph-capturable: kernel launches only, default stream => serialized)
// ---------------------------------------------------------------------------
extern "C" void kernel_launch(void* const* d_in, const int* in_sizes, int n_in,
                              void* d_out, int out_size) {
    const float* x  = (const float*)d_in[0];
    const float* Wq = (const float*)d_in[1];
    const float* bq = (const float*)d_in[2];
    const float* Wk = (const float*)d_in[3];
    const float* bk = (const float*)d_in[4];
    const float* Wv = (const float*)d_in[5];
    const float* bv = (const float*)d_in[6];
    float* out = (float*)d_out;

    // out[..., 0:512] = x
    copy_x_kernel<<<ROWS * (DMODEL / 4) / 256, 256>>>(x, out);

    // Q/K/V = x @ W* + b*
    qkv_gemm_kernel<<<dim3(4, 128, 3), 256>>>(x, Wq, bq, Wk, bk, Wv, bv);

    // causal attention -> out[..., 512:1024]
    attn_kernel<<<dim3(SEQ / BQ, BATCH), 256>>>(out);
}